// round 16
// baseline (speedup 1.0000x reference)
#include <cuda_runtime.h>
#include <cuda_bf16.h>

// Problem constants
#define BATCH 4
#define LSEQ  4096
#define DIN   256      // D_INNER
#define PDIM  512      // 2*D_INNER
#define NRROW 40       // DT_RANK + 2*D_STATE
#define NST   16       // D_STATE
#define DTR   8        // DT_RANK

// ---------------- scratch (static __device__, allocation-free) ----------------
__device__ float g_xz [BATCH*PDIM*LSEQ];    // in_proj output, original l-order
__device__ float g_xzs[BATCH*PDIM*LSEQ];    // slice-permuted xz (t-order)
__device__ float g_xc [3*BATCH*DIN*LSEQ];   // conv+silu output per dir (t-order)
__device__ float g_bc [3*BATCH*NRROW*LSEQ]; // x_proj output: dt_raw/B/C rows (t-order)
__device__ float g_y  [3*BATCH*DIN*LSEQ];   // per-dir y in original l-order
__device__ float g_yt [BATCH*DIN*LSEQ];     // slice-dir y in t-order (pre-unpermute)

__device__ __forceinline__ float ex2_approx(float x) {
  float r;
  asm("ex2.approx.f32 %0, %1;" : "=f"(r) : "f"(x));
  return r;
}

// ---------------- 1) in_proj: xz[b][p][l] = W[p][d] * x[b][l][d] ----------------
// grid (L/64, P/128, B), block 256
__global__ __launch_bounds__(256) void k_inproj(const float* __restrict__ x,
                                                const float* __restrict__ W) {
  __shared__ __align__(16) float Ws[32][132];  // [k][p-tile 128]
  __shared__ __align__(16) float Xs[32][68];   // [k][l-tile 64]
  const int b = blockIdx.z, pb = blockIdx.y * 128, l0 = blockIdx.x * 64;
  const int tid = threadIdx.x;
  const int tp = tid >> 4, tl = tid & 15;   // tp: 16 groups of 8 p; tl: 16 groups of 4 l
  float acc[8][4];
  #pragma unroll
  for (int i = 0; i < 8; i++)
    #pragma unroll
    for (int j = 0; j < 4; j++) acc[i][j] = 0.f;

  for (int kc = 0; kc < 128; kc += 32) {
    for (int e = tid; e < 128*32; e += 256) {
      int pr = e >> 5, kk = e & 31;
      Ws[kk][pr] = W[(pb + pr)*128 + kc + kk];
    }
    for (int e = tid; e < 64*32; e += 256) {
      int lr = e >> 5, kk = e & 31;
      Xs[kk][lr] = x[((size_t)b*LSEQ + l0 + lr)*128 + kc + kk];
    }
    __syncthreads();
    #pragma unroll
    for (int k = 0; k < 32; k++) {
      float4 wa = *(const float4*)&Ws[k][tp*8];
      float4 wb = *(const float4*)&Ws[k][tp*8+4];
      float4 xv = *(const float4*)&Xs[k][tl*4];
      float wr[8] = {wa.x,wa.y,wa.z,wa.w, wb.x,wb.y,wb.z,wb.w};
      float xr[4] = {xv.x,xv.y,xv.z,xv.w};
      #pragma unroll
      for (int i = 0; i < 8; i++)
        #pragma unroll
        for (int j = 0; j < 4; j++) acc[i][j] = fmaf(wr[i], xr[j], acc[i][j]);
    }
    __syncthreads();
  }
  #pragma unroll
  for (int i = 0; i < 8; i++) {
    float4 v = make_float4(acc[i][0], acc[i][1], acc[i][2], acc[i][3]);
    *(float4*)&g_xz[((size_t)b*PDIM + pb + tp*8 + i)*LSEQ + l0 + tl*4] = v;
  }
}

// ---------------- 2) slice permute: g_xzs[row][16j+s] = g_xz[row][256s+j] -------
// grid (BATCH*PDIM), block 256
__global__ __launch_bounds__(256) void k_perm_fwd() {
  __shared__ float tile[16][65];
  const float* __restrict__ s = g_xz + (size_t)blockIdx.x * LSEQ;
  float* __restrict__ d = g_xzs + (size_t)blockIdx.x * LSEQ;
  const int tid = threadIdx.x;
  for (int jc = 0; jc < 256; jc += 64) {
    #pragma unroll
    for (int p = 0; p < 4; p++) {
      int jj = tid & 63, sv = p*4 + (tid >> 6);
      tile[sv][jj] = s[256*sv + jc + jj];
    }
    __syncthreads();
    #pragma unroll
    for (int p = 0; p < 4; p++) {
      int e = p*256 + tid;
      d[16*jc + e] = tile[e & 15][e >> 4];
    }
    __syncthreads();
  }
}

// ---------------- 3) causal depthwise conv (D_CONV=4) + SiLU, per dir ----------
// grid (L/1024, DIN, 4), block 256, one launch per dir
__global__ __launch_bounds__(256) void k_conv(const float* __restrict__ cw_all,
                                              const float* __restrict__ cb_all,
                                              int dir) {
  __shared__ float xs[1027];
  const int b = blockIdx.z & 3;
  const int dirb = dir*4 + b;
  const int c = blockIdx.y, t0 = blockIdx.x * 1024;
  const float* __restrict__ row = (dir == 2 ? g_xzs : g_xz) + ((size_t)b*PDIM + c)*LSEQ;
  for (int e = threadIdx.x; e < 1027; e += 256) {
    int t = t0 - 3 + e;
    float v = 0.f;
    if (t >= 0) v = row[(dir == 1) ? (LSEQ-1 - t) : t];
    xs[e] = v;
  }
  __syncthreads();
  const float* cw = cw_all + c*4;
  float w0 = cw[0], w1 = cw[1], w2 = cw[2], w3 = cw[3];
  float bb = cb_all[c];
  int base = threadIdx.x * 4;
  float o[4];
  #pragma unroll
  for (int q = 0; q < 4; q++) {
    float a = bb;
    a = fmaf(w0, xs[base+q+0], a);
    a = fmaf(w1, xs[base+q+1], a);
    a = fmaf(w2, xs[base+q+2], a);
    a = fmaf(w3, xs[base+q+3], a);
    o[q] = a / (1.f + __expf(-a));  // silu
  }
  float4 v = make_float4(o[0], o[1], o[2], o[3]);
  *(float4*)&g_xc[((size_t)dirb*DIN + c)*LSEQ + t0 + base] = v;
}

// ---------------- 4) x_proj: bc[r][t] = xproj[r][c] * xc[c][t], r<40 -----------
// grid (L/128, 4), block 256, one launch per dir
__global__ __launch_bounds__(256) void k_xproj(const float* __restrict__ Wp, int dir) {
  __shared__ __align__(16) float Ws[64][44];   // [k][r 40]
  __shared__ __align__(16) float Xs[64][132];  // [k][t 128]
  const int dirb = dir*4 + blockIdx.y;
  const int t0 = blockIdx.x * 128;
  const int tid = threadIdx.x;
  const int rg = tid >> 6, tt = tid & 63;   // 4 r-groups of 10, 64 t-groups of 2
  float acc[10][2];
  #pragma unroll
  for (int i = 0; i < 10; i++) { acc[i][0] = 0.f; acc[i][1] = 0.f; }

  for (int kc = 0; kc < DIN; kc += 64) {
    for (int e = tid; e < 40*64; e += 256) {
      int r = e >> 6, k = e & 63;
      Ws[k][r] = Wp[r*DIN + kc + k];
    }
    for (int f = tid; f < 2048; f += 256) {
      int k = f >> 5, c4 = f & 31;
      *(float4*)&Xs[k][c4*4] =
        *(const float4*)&g_xc[((size_t)dirb*DIN + kc + k)*LSEQ + t0 + c4*4];
    }
    __syncthreads();
    #pragma unroll 4
    for (int k = 0; k < 64; k++) {
      float xa = Xs[k][2*tt], xb = Xs[k][2*tt+1];
      #pragma unroll
      for (int i = 0; i < 10; i++) {
        float wv = Ws[k][rg*10 + i];
        acc[i][0] = fmaf(wv, xa, acc[i][0]);
        acc[i][1] = fmaf(wv, xb, acc[i][1]);
      }
    }
    __syncthreads();
  }
  #pragma unroll
  for (int i = 0; i < 10; i++) {
    *(float2*)&g_bc[((size_t)dirb*NRROW + rg*10 + i)*LSEQ + t0 + 2*tt] =
      make_float2(acc[i][0], acc[i][1]);
  }
}

// ---------------- 5) selective scan + fused delta + gate -----------------------
// grid (12, DIN/4), block 64 — SINGLE launch covering all 3 dirs for full
// concurrency (1536 warps chip-wide); 16 lanes (=states) per (dir,b,d) channel.
__global__ __launch_bounds__(64) void k_scan(
    const float* __restrict__ dtw0,  const float* __restrict__ dtb0,
    const float* __restrict__ Alog0, const float* __restrict__ Dvec0,
    const float* __restrict__ dtw1,  const float* __restrict__ dtb1,
    const float* __restrict__ Alog1, const float* __restrict__ Dvec1,
    const float* __restrict__ dtw2,  const float* __restrict__ dtb2,
    const float* __restrict__ Alog2, const float* __restrict__ Dvec2) {
  const int db = blockIdx.x;              // dir*4 + b
  const int dir = db >> 2, b = db & 3;
  const float* dtw  = (dir == 0) ? dtw0  : (dir == 1) ? dtw1  : dtw2;
  const float* dtb  = (dir == 0) ? dtb0  : (dir == 1) ? dtb1  : dtb2;
  const float* Alog = (dir == 0) ? Alog0 : (dir == 1) ? Alog1 : Alog2;
  const float* Dvec = (dir == 0) ? Dvec0 : (dir == 1) ? Dvec1 : Dvec2;

  const int g = threadIdx.x >> 4, lane = threadIdx.x & 15;
  const int d = blockIdx.y * 4 + g;
  const float* __restrict__ u_row  = g_xc + ((size_t)db*DIN + d)*LSEQ;
  const float* __restrict__ raw0   = g_bc + (size_t)db*NRROW*LSEQ;       // rows 0..7: dt_raw
  const float* __restrict__ B_row  = g_bc + ((size_t)db*NRROW + DTR + lane)*LSEQ;
  const float* __restrict__ C_row  = g_bc + ((size_t)db*NRROW + DTR + NST + lane)*LSEQ;
  const float* __restrict__ z_row  = (dir == 2 ? g_xzs : g_xz) + ((size_t)b*PDIM + DIN + d)*LSEQ;
  float* __restrict__ y_row = (dir == 2) ? (g_yt + ((size_t)b*DIN + d)*LSEQ)
                                         : (g_y  + ((size_t)db*DIN + d)*LSEQ);
  // A2 = A * log2(e) so dA = ex2(dl * A2)  (one MUFU, no extra FMUL per step)
  const float A2 = -__expf(Alog[d*NST + lane]) * 1.44269504089f;
  const float Dp = Dvec[d];
  // dt_proj row for this channel (8 weights + bias), same for all 16 lanes
  float4 wv0 = *(const float4*)(dtw + d*DTR);
  float4 wv1 = *(const float4*)(dtw + d*DTR + 4);
  const float dtb_d = dtb[d];
  const float wr[8] = {wv0.x,wv0.y,wv0.z,wv0.w, wv1.x,wv1.y,wv1.z,wv1.w};

  float h = 0.f;
  const bool hi8 = (lane & 8) != 0, hi4 = (lane & 4) != 0;
  const bool hi2 = (lane & 2) != 0, hi1 = (lane & 1) != 0;

  for (int t0 = 0; t0 < LSEQ; t0 += 16) {
    const int t = t0 + lane;
    // fused delta = softplus(dtw . raw + dtb) at own t
    float a = dtb_d;
    #pragma unroll
    for (int r = 0; r < 8; r++) a = fmaf(wr[r], raw0[(size_t)r*LSEQ + t], a);
    float dl = (a > 20.f) ? a : __logf(1.f + __expf(a));
    float u  = u_row[t];
    float du = dl * u;
    // B/C for own state across the 16 times of the tile
    float Br[16], Cr[16];
    const float4* bp = (const float4*)(B_row + t0);
    const float4* cp = (const float4*)(C_row + t0);
    #pragma unroll
    for (int q = 0; q < 4; q++) {
      float4 v = bp[q];
      Br[4*q+0]=v.x; Br[4*q+1]=v.y; Br[4*q+2]=v.z; Br[4*q+3]=v.w;
      float4 w = cp[q];
      Cr[4*q+0]=w.x; Cr[4*q+1]=w.y; Cr[4*q+2]=w.z; Cr[4*q+3]=w.w;
    }
    // sequential recurrence over the 16 times; lane = state
    float p[16];
    #pragma unroll
    for (int j = 0; j < 16; j++) {
      float dlj = __shfl_sync(0xffffffffu, dl, j, 16);
      float duj = __shfl_sync(0xffffffffu, du, j, 16);
      float dA = ex2_approx(dlj * A2);
      h = fmaf(h, dA, duj * Br[j]);
      p[j] = h * Cr[j];
    }
    // butterfly transpose-reduce: y_j = sum_n p_n[j], result lands on lane j
    float v8[8];
    #pragma unroll
    for (int i = 0; i < 8; i++) {
      float send = hi8 ? p[i] : p[i+8];
      float keep = hi8 ? p[i+8] : p[i];
      v8[i] = keep + __shfl_xor_sync(0xffffffffu, send, 8, 16);
    }
    float v4[4];
    #pragma unroll
    for (int i = 0; i < 4; i++) {
      float send = hi4 ? v8[i] : v8[i+4];
      float keep = hi4 ? v8[i+4] : v8[i];
      v4[i] = keep + __shfl_xor_sync(0xffffffffu, send, 4, 16);
    }
    float v2[2];
    #pragma unroll
    for (int i = 0; i < 2; i++) {
      float send = hi2 ? v4[i] : v4[i+2];
      float keep = hi2 ? v4[i+2] : v4[i];
      v2[i] = keep + __shfl_xor_sync(0xffffffffu, send, 2, 16);
    }
    float send = hi1 ? v2[0] : v2[1];
    float keep = hi1 ? v2[1] : v2[0];
    float yv = keep + __shfl_xor_sync(0xffffffffu, send, 1, 16);
    // gate + D skip, store (un-flip for backward dir)
    float z = (dir == 1) ? z_row[LSEQ-1 - t] : z_row[t];
    float sz = z / (1.f + __expf(-z));
    float outv = (yv + Dp * u) * sz;
    if (dir == 1) y_row[LSEQ-1 - t] = outv;
    else          y_row[t] = outv;
  }
}

// ---------------- 6) un-permute slice-dir y: y[256s+j] = yt[16j+s] -------------
// grid (BATCH*DIN), block 256
__global__ __launch_bounds__(256) void k_perm_bwd() {
  __shared__ float tile[16][65];
  const float* __restrict__ s = g_yt + (size_t)blockIdx.x * LSEQ;
  float* __restrict__ d = g_y + (size_t)(2*BATCH*DIN)*LSEQ + (size_t)blockIdx.x * LSEQ;
  const int tid = threadIdx.x;
  for (int jc = 0; jc < 256; jc += 64) {
    #pragma unroll
    for (int p = 0; p < 4; p++) {
      int e = p*256 + tid;
      tile[e & 15][e >> 4] = s[16*jc + e];
    }
    __syncthreads();
    #pragma unroll
    for (int p = 0; p < 4; p++) {
      int jj = tid & 63, sv = p*4 + (tid >> 6);
      d[256*sv + jc + jj] = tile[sv][jj];
    }
    __syncthreads();
  }
}

// ---------------- 7) out_proj: out[b][l][o] = W[o][d] * sum_dirs y[b][d][l] ----
// grid (L/32, B), block 256
__global__ __launch_bounds__(256) void k_outproj(const float* __restrict__ W,
                                                 float* __restrict__ out) {
  __shared__ __align__(16) float Ws[64][132];  // [k][o 128]
  __shared__ __align__(16) float Ys[64][36];   // [k][l 32]
  const int b = blockIdx.y, l0 = blockIdx.x * 32;
  const int tid = threadIdx.x;
  const int o0 = (tid & 31) * 4, lq = tid >> 5;
  float acc[4][4];  // [li][oi]
  #pragma unroll
  for (int i = 0; i < 4; i++)
    #pragma unroll
    for (int j = 0; j < 4; j++) acc[i][j] = 0.f;

  const size_t dstride = (size_t)BATCH*DIN*LSEQ;
  for (int kc = 0; kc < DIN; kc += 64) {
    for (int f = tid; f < 2048; f += 256) {
      int o = f >> 4, k4 = f & 15;
      float4 v = *(const float4*)&W[o*DIN + kc + 4*k4];
      Ws[4*k4+0][o] = v.x; Ws[4*k4+1][o] = v.y;
      Ws[4*k4+2][o] = v.z; Ws[4*k4+3][o] = v.w;
    }
    for (int e = tid; e < 2048; e += 256) {
      int k = e >> 5, j = e & 31;
      size_t i0 = ((size_t)b*DIN + kc + k)*LSEQ + l0 + j;
      Ys[k][j] = g_y[i0] + g_y[i0 + dstride] + g_y[i0 + 2*dstride];
    }
    __syncthreads();
    #pragma unroll 4
    for (int k = 0; k < 64; k++) {
      float4 wv = *(const float4*)&Ws[k][o0];
      float4 yv = *(const float4*)&Ys[k][lq*4];
      float wr[4] = {wv.x,wv.y,wv.z,wv.w};
      float yr[4] = {yv.x,yv.y,yv.z,yv.w};
      #pragma unroll
      for (int i = 0; i < 4; i++)
        #pragma unroll
        for (int j = 0; j < 4; j++) acc[i][j] = fmaf(wr[j], yr[i], acc[i][j]);
    }
    __syncthreads();
  }
  #pragma unroll
  for (int i = 0; i < 4; i++) {
    float4 v = make_float4(acc[i][0], acc[i][1], acc[i][2], acc[i][3]);
    *(float4*)&out[((size_t)b*LSEQ + l0 + lq*4 + i)*128 + o0] = v;
  }
}

// ---------------- launch ----------------
extern "C" void kernel_launch(void* const* d_in, const int* in_sizes, int n_in,
                              void* d_out, int out_size) {
  const float* x_in = (const float*)d_in[0];
  const float* in_proj_w = (const float*)d_in[1];
  const float* out_proj_w = (const float*)d_in[23];
  float* out = (float*)d_out;

  k_inproj  <<<dim3(LSEQ/64, PDIM/128, BATCH), 256>>>(x_in, in_proj_w);
  k_perm_fwd<<<BATCH*PDIM, 256>>>();
  for (int dir = 0; dir < 3; dir++) {
    int base = 2 + 7*dir;
    k_conv<<<dim3(LSEQ/1024, DIN, 4), 256>>>(
        (const float*)d_in[base + 0], (const float*)d_in[base + 1], dir);
  }
  for (int dir = 0; dir < 3; dir++) {
    k_xproj<<<dim3(LSEQ/128, 4), 256>>>((const float*)d_in[2 + 7*dir + 2], dir);
  }
  k_scan<<<dim3(12, DIN/4), 64>>>(
      (const float*)d_in[5],  (const float*)d_in[6],  (const float*)d_in[7],  (const float*)d_in[8],
      (const float*)d_in[12], (const float*)d_in[13], (const float*)d_in[14], (const float*)d_in[15],
      (const float*)d_in[19], (const float*)d_in[20], (const float*)d_in[21], (const float*)d_in[22]);
  k_perm_bwd<<<BATCH*DIN, 256>>>();
  k_outproj <<<dim3(LSEQ/32, BATCH), 256>>>(out_proj_w, out);
}

// round 17
// speedup vs baseline: 1.1015x; 1.1015x over previous
#include <cuda_runtime.h>
#include <cuda_bf16.h>

// Problem constants
#define BATCH 4
#define LSEQ  4096
#define DIN   256      // D_INNER
#define PDIM  512      // 2*D_INNER
#define NRROW 40       // DT_RANK + 2*D_STATE
#define NST   16       // D_STATE
#define DTR   8        // DT_RANK

// ---------------- scratch (static __device__, allocation-free) ----------------
__device__ float g_xz [BATCH*PDIM*LSEQ];    // in_proj output, original l-order
__device__ float g_xzs[BATCH*PDIM*LSEQ];    // slice-permuted xz (t-order)
__device__ float g_xc [3*BATCH*DIN*LSEQ];   // conv+silu output per dir (t-order)
__device__ float g_bc [3*BATCH*NRROW*LSEQ]; // x_proj output: dt_raw/B/C rows (t-order)
__device__ float g_y  [3*BATCH*DIN*LSEQ];   // per-dir y in original l-order
__device__ float g_yt [BATCH*DIN*LSEQ];     // slice-dir y in t-order (pre-unpermute)

__device__ __forceinline__ float ex2_approx(float x) {
  float r;
  asm("ex2.approx.f32 %0, %1;" : "=f"(r) : "f"(x));
  return r;
}

// Packed fp32x2 FMA (sm_103a; elementwise RN — bit-identical to two FFMAs)
__device__ __forceinline__ void ffma2(float2& d, float2 a, float2 b) {
  asm("fma.rn.f32x2 %0, %1, %2, %0;"
      : "+l"(*reinterpret_cast<unsigned long long*>(&d))
      : "l"(*reinterpret_cast<const unsigned long long*>(&a)),
        "l"(*reinterpret_cast<const unsigned long long*>(&b)));
}

// ---------------- 1) in_proj: xz[b][p][l] = W[p][d] * x[b][l][d] ----------------
// grid (L/64, P/128, B), block 256; FFMA2 inner loop (pairs along p)
__global__ __launch_bounds__(256) void k_inproj(const float* __restrict__ x,
                                                const float* __restrict__ W) {
  __shared__ __align__(16) float Ws[32][132];  // [k][p-tile 128]
  __shared__ __align__(16) float Xs[32][68];   // [k][l-tile 64]
  const int b = blockIdx.z, pb = blockIdx.y * 128, l0 = blockIdx.x * 64;
  const int tid = threadIdx.x;
  const int tp = tid >> 4, tl = tid & 15;   // tp: 16 groups of 8 p; tl: 16 groups of 4 l
  float2 accp[4][4];   // [p-pair][l]; pair = (p=2ip, p=2ip+1)
  #pragma unroll
  for (int i = 0; i < 4; i++)
    #pragma unroll
    for (int j = 0; j < 4; j++) accp[i][j] = make_float2(0.f, 0.f);

  for (int kc = 0; kc < 128; kc += 32) {
    for (int e = tid; e < 128*32; e += 256) {
      int pr = e >> 5, kk = e & 31;
      Ws[kk][pr] = W[(pb + pr)*128 + kc + kk];
    }
    for (int e = tid; e < 64*32; e += 256) {
      int lr = e >> 5, kk = e & 31;
      Xs[kk][lr] = x[((size_t)b*LSEQ + l0 + lr)*128 + kc + kk];
    }
    __syncthreads();
    #pragma unroll
    for (int k = 0; k < 32; k++) {
      float4 wa = *(const float4*)&Ws[k][tp*8];
      float4 wb = *(const float4*)&Ws[k][tp*8+4];
      float4 xv = *(const float4*)&Xs[k][tl*4];
      float2 ap[4] = { make_float2(wa.x,wa.y), make_float2(wa.z,wa.w),
                       make_float2(wb.x,wb.y), make_float2(wb.z,wb.w) };
      float xr[4] = {xv.x,xv.y,xv.z,xv.w};
      #pragma unroll
      for (int j = 0; j < 4; j++) {
        float2 bj = make_float2(xr[j], xr[j]);
        #pragma unroll
        for (int i = 0; i < 4; i++) ffma2(accp[i][j], ap[i], bj);
      }
    }
    __syncthreads();
  }
  #pragma unroll
  for (int i = 0; i < 4; i++) {
    float4 v0 = make_float4(accp[i][0].x, accp[i][1].x, accp[i][2].x, accp[i][3].x);
    float4 v1 = make_float4(accp[i][0].y, accp[i][1].y, accp[i][2].y, accp[i][3].y);
    *(float4*)&g_xz[((size_t)b*PDIM + pb + tp*8 + 2*i    )*LSEQ + l0 + tl*4] = v0;
    *(float4*)&g_xz[((size_t)b*PDIM + pb + tp*8 + 2*i + 1)*LSEQ + l0 + tl*4] = v1;
  }
}

// ---------------- 2) slice permute: g_xzs[row][16j+s] = g_xz[row][256s+j] -------
// grid (BATCH*PDIM), block 256
__global__ __launch_bounds__(256) void k_perm_fwd() {
  __shared__ float tile[16][65];
  const float* __restrict__ s = g_xz + (size_t)blockIdx.x * LSEQ;
  float* __restrict__ d = g_xzs + (size_t)blockIdx.x * LSEQ;
  const int tid = threadIdx.x;
  for (int jc = 0; jc < 256; jc += 64) {
    #pragma unroll
    for (int p = 0; p < 4; p++) {
      int jj = tid & 63, sv = p*4 + (tid >> 6);
      tile[sv][jj] = s[256*sv + jc + jj];
    }
    __syncthreads();
    #pragma unroll
    for (int p = 0; p < 4; p++) {
      int e = p*256 + tid;
      d[16*jc + e] = tile[e & 15][e >> 4];
    }
    __syncthreads();
  }
}

// ---------------- 3) causal depthwise conv (D_CONV=4) + SiLU, all dirs ---------
// grid (L/1024, DIN, 12), block 256; blockIdx.z = dir*4 + b (single launch)
__global__ __launch_bounds__(256) void k_conv(
    const float* __restrict__ cw0, const float* __restrict__ cb0,
    const float* __restrict__ cw1, const float* __restrict__ cb1,
    const float* __restrict__ cw2, const float* __restrict__ cb2) {
  __shared__ float xs[1027];
  const int dirb = blockIdx.z, dir = dirb >> 2, b = dirb & 3;
  const float* cw_all = (dir == 0) ? cw0 : (dir == 1) ? cw1 : cw2;
  const float* cb_all = (dir == 0) ? cb0 : (dir == 1) ? cb1 : cb2;
  const int c = blockIdx.y, t0 = blockIdx.x * 1024;
  const float* __restrict__ row = (dir == 2 ? g_xzs : g_xz) + ((size_t)b*PDIM + c)*LSEQ;
  for (int e = threadIdx.x; e < 1027; e += 256) {
    int t = t0 - 3 + e;
    float v = 0.f;
    if (t >= 0) v = row[(dir == 1) ? (LSEQ-1 - t) : t];
    xs[e] = v;
  }
  __syncthreads();
  const float* cw = cw_all + c*4;
  float w0 = cw[0], w1 = cw[1], w2 = cw[2], w3 = cw[3];
  float bb = cb_all[c];
  int base = threadIdx.x * 4;
  float o[4];
  #pragma unroll
  for (int q = 0; q < 4; q++) {
    float a = bb;
    a = fmaf(w0, xs[base+q+0], a);
    a = fmaf(w1, xs[base+q+1], a);
    a = fmaf(w2, xs[base+q+2], a);
    a = fmaf(w3, xs[base+q+3], a);
    o[q] = a / (1.f + __expf(-a));  // silu
  }
  float4 v = make_float4(o[0], o[1], o[2], o[3]);
  *(float4*)&g_xc[((size_t)dirb*DIN + c)*LSEQ + t0 + base] = v;
}

// ---------------- 4) x_proj: bc[r][t] = xproj[r][c] * xc[c][t], r<40 -----------
// grid (L/128, 12), block 256; blockIdx.y = dir*4 + b (single launch)
__global__ __launch_bounds__(256) void k_xproj(
    const float* __restrict__ W0, const float* __restrict__ W1,
    const float* __restrict__ W2) {
  __shared__ __align__(16) float Ws[64][44];   // [k][r 40]
  __shared__ __align__(16) float Xs[64][132];  // [k][t 128]
  const int dirb = blockIdx.y, dir = dirb >> 2;
  const float* __restrict__ Wp = (dir == 0) ? W0 : (dir == 1) ? W1 : W2;
  const int t0 = blockIdx.x * 128;
  const int tid = threadIdx.x;
  const int rg = tid >> 6, tt = tid & 63;   // 4 r-groups of 10, 64 t-groups of 2
  float acc[10][2];
  #pragma unroll
  for (int i = 0; i < 10; i++) { acc[i][0] = 0.f; acc[i][1] = 0.f; }

  for (int kc = 0; kc < DIN; kc += 64) {
    for (int e = tid; e < 40*64; e += 256) {
      int r = e >> 6, k = e & 63;
      Ws[k][r] = Wp[r*DIN + kc + k];
    }
    for (int f = tid; f < 2048; f += 256) {
      int k = f >> 5, c4 = f & 31;
      *(float4*)&Xs[k][c4*4] =
        *(const float4*)&g_xc[((size_t)dirb*DIN + kc + k)*LSEQ + t0 + c4*4];
    }
    __syncthreads();
    #pragma unroll 4
    for (int k = 0; k < 64; k++) {
      float xa = Xs[k][2*tt], xb = Xs[k][2*tt+1];
      #pragma unroll
      for (int i = 0; i < 10; i++) {
        float wv = Ws[k][rg*10 + i];
        acc[i][0] = fmaf(wv, xa, acc[i][0]);
        acc[i][1] = fmaf(wv, xb, acc[i][1]);
      }
    }
    __syncthreads();
  }
  #pragma unroll
  for (int i = 0; i < 10; i++) {
    *(float2*)&g_bc[((size_t)dirb*NRROW + rg*10 + i)*LSEQ + t0 + 2*tt] =
      make_float2(acc[i][0], acc[i][1]);
  }
}

// ---------------- 5) selective scan + fused delta + gate -----------------------
// grid (12, DIN/4), block 64 — single launch, all 3 dirs (1536 warps chip-wide);
// 16 lanes (=states) per (dir,b,d) channel, 4 channels per block.
__global__ __launch_bounds__(64) void k_scan(
    const float* __restrict__ dtw0,  const float* __restrict__ dtb0,
    const float* __restrict__ Alog0, const float* __restrict__ Dvec0,
    const float* __restrict__ dtw1,  const float* __restrict__ dtb1,
    const float* __restrict__ Alog1, const float* __restrict__ Dvec1,
    const float* __restrict__ dtw2,  const float* __restrict__ dtb2,
    const float* __restrict__ Alog2, const float* __restrict__ Dvec2) {
  const int db = blockIdx.x;              // dir*4 + b
  const int dir = db >> 2, b = db & 3;
  const float* dtw  = (dir == 0) ? dtw0  : (dir == 1) ? dtw1  : dtw2;
  const float* dtb  = (dir == 0) ? dtb0  : (dir == 1) ? dtb1  : dtb2;
  const float* Alog = (dir == 0) ? Alog0 : (dir == 1) ? Alog1 : Alog2;
  const float* Dvec = (dir == 0) ? Dvec0 : (dir == 1) ? Dvec1 : Dvec2;

  const int g = threadIdx.x >> 4, lane = threadIdx.x & 15;
  const int d = blockIdx.y * 4 + g;
  const float* __restrict__ u_row  = g_xc + ((size_t)db*DIN + d)*LSEQ;
  const float* __restrict__ raw0   = g_bc + (size_t)db*NRROW*LSEQ;       // rows 0..7: dt_raw
  const float* __restrict__ B_row  = g_bc + ((size_t)db*NRROW + DTR + lane)*LSEQ;
  const float* __restrict__ C_row  = g_bc + ((size_t)db*NRROW + DTR + NST + lane)*LSEQ;
  const float* __restrict__ z_row  = (dir == 2 ? g_xzs : g_xz) + ((size_t)b*PDIM + DIN + d)*LSEQ;
  float* __restrict__ y_row = (dir == 2) ? (g_yt + ((size_t)b*DIN + d)*LSEQ)
                                         : (g_y  + ((size_t)db*DIN + d)*LSEQ);
  // A2 = A * log2(e) so dA = ex2(dl * A2)  (one MUFU, no extra FMUL per step)
  const float A2 = -__expf(Alog[d*NST + lane]) * 1.44269504089f;
  const float Dp = Dvec[d];
  // dt_proj row for this channel (8 weights + bias), same for all 16 lanes
  float4 wv0 = *(const float4*)(dtw + d*DTR);
  float4 wv1 = *(const float4*)(dtw + d*DTR + 4);
  const float dtb_d = dtb[d];
  const float wr[8] = {wv0.x,wv0.y,wv0.z,wv0.w, wv1.x,wv1.y,wv1.z,wv1.w};

  float h = 0.f;
  const bool hi8 = (lane & 8) != 0, hi4 = (lane & 4) != 0;
  const bool hi2 = (lane & 2) != 0, hi1 = (lane & 1) != 0;

  for (int t0 = 0; t0 < LSEQ; t0 += 16) {
    const int t = t0 + lane;
    // fused delta = softplus(dtw . raw + dtb) at own t
    float a = dtb_d;
    #pragma unroll
    for (int r = 0; r < 8; r++) a = fmaf(wr[r], raw0[(size_t)r*LSEQ + t], a);
    float dl = (a > 20.f) ? a : __logf(1.f + __expf(a));
    float u  = u_row[t];
    float du = dl * u;
    // B/C for own state across the 16 times of the tile
    float Br[16], Cr[16];
    const float4* bp = (const float4*)(B_row + t0);
    const float4* cp = (const float4*)(C_row + t0);
    #pragma unroll
    for (int q = 0; q < 4; q++) {
      float4 v = bp[q];
      Br[4*q+0]=v.x; Br[4*q+1]=v.y; Br[4*q+2]=v.z; Br[4*q+3]=v.w;
      float4 w = cp[q];
      Cr[4*q+0]=w.x; Cr[4*q+1]=w.y; Cr[4*q+2]=w.z; Cr[4*q+3]=w.w;
    }
    // sequential recurrence over the 16 times; lane = state
    float p[16];
    #pragma unroll
    for (int j = 0; j < 16; j++) {
      float dlj = __shfl_sync(0xffffffffu, dl, j, 16);
      float duj = __shfl_sync(0xffffffffu, du, j, 16);
      float dA = ex2_approx(dlj * A2);
      h = fmaf(h, dA, duj * Br[j]);
      p[j] = h * Cr[j];
    }
    // butterfly transpose-reduce: y_j = sum_n p_n[j], result lands on lane j
    float v8[8];
    #pragma unroll
    for (int i = 0; i < 8; i++) {
      float send = hi8 ? p[i] : p[i+8];
      float keep = hi8 ? p[i+8] : p[i];
      v8[i] = keep + __shfl_xor_sync(0xffffffffu, send, 8, 16);
    }
    float v4[4];
    #pragma unroll
    for (int i = 0; i < 4; i++) {
      float send = hi4 ? v8[i] : v8[i+4];
      float keep = hi4 ? v8[i+4] : v8[i];
      v4[i] = keep + __shfl_xor_sync(0xffffffffu, send, 4, 16);
    }
    float v2[2];
    #pragma unroll
    for (int i = 0; i < 2; i++) {
      float send = hi2 ? v4[i] : v4[i+2];
      float keep = hi2 ? v4[i+2] : v4[i];
      v2[i] = keep + __shfl_xor_sync(0xffffffffu, send, 2, 16);
    }
    float send = hi1 ? v2[0] : v2[1];
    float keep = hi1 ? v2[1] : v2[0];
    float yv = keep + __shfl_xor_sync(0xffffffffu, send, 1, 16);
    // gate + D skip, store (un-flip for backward dir)
    float z = (dir == 1) ? z_row[LSEQ-1 - t] : z_row[t];
    float sz = z / (1.f + __expf(-z));
    float outv = (yv + Dp * u) * sz;
    if (dir == 1) y_row[LSEQ-1 - t] = outv;
    else          y_row[t] = outv;
  }
}

// ---------------- 6) un-permute slice-dir y: y[256s+j] = yt[16j+s] -------------
// grid (BATCH*DIN), block 256
__global__ __launch_bounds__(256) void k_perm_bwd() {
  __shared__ float tile[16][65];
  const float* __restrict__ s = g_yt + (size_t)blockIdx.x * LSEQ;
  float* __restrict__ d = g_y + (size_t)(2*BATCH*DIN)*LSEQ + (size_t)blockIdx.x * LSEQ;
  const int tid = threadIdx.x;
  for (int jc = 0; jc < 256; jc += 64) {
    #pragma unroll
    for (int p = 0; p < 4; p++) {
      int e = p*256 + tid;
      tile[e & 15][e >> 4] = s[16*jc + e];
    }
    __syncthreads();
    #pragma unroll
    for (int p = 0; p < 4; p++) {
      int jj = tid & 63, sv = p*4 + (tid >> 6);
      d[256*sv + jc + jj] = tile[sv][jj];
    }
    __syncthreads();
  }
}

// ---------------- 7) out_proj: out[b][l][o] = W[o][d] * sum_dirs y[b][d][l] ----
// grid (L/32, B), block 256; FFMA2 inner loop (pairs along o)
__global__ __launch_bounds__(256) void k_outproj(const float* __restrict__ W,
                                                 float* __restrict__ out) {
  __shared__ __align__(16) float Ws[64][132];  // [k][o 128]
  __shared__ __align__(16) float Ys[64][36];   // [k][l 32]
  const int b = blockIdx.y, l0 = blockIdx.x * 32;
  const int tid = threadIdx.x;
  const int o0 = (tid & 31) * 4, lq = tid >> 5;
  float2 accp[4][2];  // [l][o-pair]; pair = (o0+2jp, o0+2jp+1)
  #pragma unroll
  for (int i = 0; i < 4; i++) {
    accp[i][0] = make_float2(0.f, 0.f);
    accp[i][1] = make_float2(0.f, 0.f);
  }

  const size_t dstride = (size_t)BATCH*DIN*LSEQ;
  for (int kc = 0; kc < DIN; kc += 64) {
    for (int f = tid; f < 2048; f += 256) {
      int o = f >> 4, k4 = f & 15;
      float4 v = *(const float4*)&W[o*DIN + kc + 4*k4];
      Ws[4*k4+0][o] = v.x; Ws[4*k4+1][o] = v.y;
      Ws[4*k4+2][o] = v.z; Ws[4*k4+3][o] = v.w;
    }
    for (int e = tid; e < 2048; e += 256) {
      int k = e >> 5, j = e & 31;
      size_t i0 = ((size_t)b*DIN + kc + k)*LSEQ + l0 + j;
      Ys[k][j] = g_y[i0] + g_y[i0 + dstride] + g_y[i0 + 2*dstride];
    }
    __syncthreads();
    #pragma unroll 4
    for (int k = 0; k < 64; k++) {
      float4 wv = *(const float4*)&Ws[k][o0];
      float4 yv = *(const float4*)&Ys[k][lq*4];
      float2 aw0 = make_float2(wv.x, wv.y);
      float2 aw1 = make_float2(wv.z, wv.w);
      float yr[4] = {yv.x,yv.y,yv.z,yv.w};
      #pragma unroll
      for (int i = 0; i < 4; i++) {
        float2 bi = make_float2(yr[i], yr[i]);
        ffma2(accp[i][0], aw0, bi);
        ffma2(accp[i][1], aw1, bi);
      }
    }
    __syncthreads();
  }
  #pragma unroll
  for (int i = 0; i < 4; i++) {
    float4 v = make_float4(accp[i][0].x, accp[i][0].y, accp[i][1].x, accp[i][1].y);
    *(float4*)&out[((size_t)b*LSEQ + l0 + lq*4 + i)*128 + o0] = v;
  }
}

// ---------------- launch ----------------
extern "C" void kernel_launch(void* const* d_in, const int* in_sizes, int n_in,
                              void* d_out, int out_size) {
  const float* x_in = (const float*)d_in[0];
  const float* in_proj_w = (const float*)d_in[1];
  const float* out_proj_w = (const float*)d_in[23];
  float* out = (float*)d_out;

  k_inproj  <<<dim3(LSEQ/64, PDIM/128, BATCH), 256>>>(x_in, in_proj_w);
  k_perm_fwd<<<BATCH*PDIM, 256>>>();
  k_conv    <<<dim3(LSEQ/1024, DIN, 12), 256>>>(
      (const float*)d_in[2],  (const float*)d_in[3],
      (const float*)d_in[9],  (const float*)d_in[10],
      (const float*)d_in[16], (const float*)d_in[17]);
  k_xproj   <<<dim3(LSEQ/128, 12), 256>>>(
      (const float*)d_in[4], (const float*)d_in[11], (const float*)d_in[18]);
  k_scan    <<<dim3(12, DIN/4), 64>>>(
      (const float*)d_in[5],  (const float*)d_in[6],  (const float*)d_in[7],  (const float*)d_in[8],
      (const float*)d_in[12], (const float*)d_in[13], (const float*)d_in[14], (const float*)d_in[15],
      (const float*)d_in[19], (const float*)d_in[20], (const float*)d_in[21], (const float*)d_in[22]);
  k_perm_bwd<<<BATCH*DIN, 256>>>();
  k_outproj <<<dim3(LSEQ/32, BATCH), 256>>>(out_proj_w, out);
}